// round 16
// baseline (speedup 1.0000x reference)
#include <cuda_runtime.h>

// ---------------------------------------------------------------------------
// GCN_84559316124289 — collapsed graph, fused conv1+conv2, ci-split warps.
//
//   P1 = pool(lrelu(conv1(x)+b1))                      (strip, smem only)
//   H2 = pool(lrelu(12*conv2w(P1) + 4*b2))             (k12_conv, 768 thr)
//   H3 = pool(lrelu(conv3(H2)+b3)); out = wc.mean+bc   (k3_conv, 768 thr)
//
// Both kernels run 6 warps/SMSP by splitting the ci loop across thread
// groups (partials combined via packed f32x2 adds through smem); per-thread
// tile and all throughput floors unchanged vs the proven R7 inner loop.
// ---------------------------------------------------------------------------

typedef unsigned long long ull;

__device__ __forceinline__ ull dup2(float x) {
    ull r; asm("mov.b64 %0, {%1, %1};" : "=l"(r) : "f"(x)); return r;
}
__device__ __forceinline__ void ffma2(ull& d, ull a, ull b) {
    asm("fma.rn.f32x2 %0, %1, %2, %0;" : "+l"(d) : "l"(a), "l"(b));
}
__device__ __forceinline__ ull addf2(ull a, ull b) {
    ull r; asm("add.rn.f32x2 %0, %1, %2;" : "=l"(r) : "l"(a), "l"(b)); return r;
}
__device__ __forceinline__ void unpk(float& lo, float& hi, ull v) {
    asm("mov.b64 {%0, %1}, %2;" : "=f"(lo), "=f"(hi) : "l"(v));
}

#define LRELU(t) ((t) > 0.f ? (t) : 0.2f * (t))

__device__ float g_H2[32 * 64 * 16 * 16];   // [B, 64, 16, 16]

// Load 4x6 patch and duplicate each value into an f32x2 register.
#define LOAD_PATCH(IB, RS)                                                     \
    ull pd[4][6];                                                              \
    _Pragma("unroll")                                                          \
    for (int r = 0; r < 4; r++) {                                              \
        float4 a4 = *(const float4*)((IB) + r * (RS));                         \
        float2 b2v = *(const float2*)((IB) + r * (RS) + 4);                    \
        pd[r][0] = dup2(a4.x);  pd[r][1] = dup2(a4.y);                         \
        pd[r][2] = dup2(a4.z);  pd[r][3] = dup2(a4.w);                         \
        pd[r][4] = dup2(b2v.x); pd[r][5] = dup2(b2v.y);                        \
    }

// Two cout-pairs (4 couts): 9 broadcast LDS.128, 16 FFMA2 / k.
#define CONV_CI_2P(IB, WP, RS, WS)                                             \
    {                                                                          \
        LOAD_PATCH(IB, RS)                                                     \
        _Pragma("unroll")                                                      \
        for (int k = 0; k < 9; k++) {                                          \
            ulonglong2 w = *(const ulonglong2*)((WP) + k * (WS));              \
            int ky = k / 3, kx = k - ky * 3;                                   \
            _Pragma("unroll")                                                  \
            for (int dy = 0; dy < 2; dy++)                                     \
                _Pragma("unroll")                                              \
                for (int dx = 0; dx < 4; dx++) {                               \
                    ull pv = pd[dy + ky][dx + kx];                             \
                    int q = dy * 4 + dx;                                       \
                    ffma2(acc[0][q], pv, w.x);                                 \
                    ffma2(acc[1][q], pv, w.y);                                 \
                }                                                              \
        }                                                                      \
    }

// ---------------------------------------------------------------------------
// Fused conv1+conv2.  grid(32, 4 strips), block 768.
// smem: s_x 6336 | s_p1 11520 | s_w1 1152 | s_w2 19584 | s_part 512*17 ull
// conv2 ci-split: tid<512 -> ci 0..20 (+combine); tid>=512 -> 2 slots, ci 21..31
// ---------------------------------------------------------------------------
__global__ void __launch_bounds__(768, 1)
k12_conv(const float* __restrict__ x,
         const float* __restrict__ w1,
         const float* __restrict__ b1,
         const float* __restrict__ w2,
         const float* __restrict__ b2,
         const float* __restrict__ bc,
         float* __restrict__ out) {
    extern __shared__ float sm[];
    float* s_x  = sm;                  // 6336
    float* s_p1 = sm + 6336;           // 11520
    float* s_w1 = sm + 17856;          // 1152
    float* s_w2 = sm + 19008;          // 19584
    ull*   s_part = (ull*)(sm + 38592);// 512*17 ull = 17408 fl  (total 56000)

    const int b  = blockIdx.x;
    const int qy = blockIdx.y;         // strip: H2 rows [4*qy, 4*qy+4)
    const int tid = threadIdx.x;

    if (qy == 0 && tid == 0) out[b] = bc[0];

    // --- stage x strip: rows gxr = 16*qy-3 .. +18, cols gxc = -3 .. 68 ---
    const float* xb = x + b * 16384;
    for (int i = tid; i < 6336; i += 768) {
        int ch = i / 1584, rem = i - ch * 1584;
        int r = rem / 72, c = rem - r * 72;
        int gxr = 16 * qy - 3 + r, gxc = c - 3;
        float v = 0.f;
        if ((unsigned)gxr < 64u && (unsigned)gxc < 64u)
            v = xb[ch * 4096 + gxr * 64 + gxc];
        s_x[i] = v;
    }
    // --- stage w1: [ci*9+k]*32 + co ---
    for (int i = tid; i < 1152; i += 768) {
        int co = i / 36, r = i - co * 36;
        s_w1[r * 32 + co] = w1[i];
    }
    // --- stage w2 (all 64 couts): [ci*9+k]*68 + co ---
    for (int i = tid * 4; i < 18432; i += 3072) {
        float4 wv = *(const float4*)(w2 + i);
        int co = i / 288, r = i - co * 288;
        s_w2[(r + 0) * 68 + co] = wv.x;
        s_w2[(r + 1) * 68 + co] = wv.y;
        s_w2[(r + 2) * 68 + co] = wv.z;
        s_w2[(r + 3) * 68 + co] = wv.w;
    }
    __syncthreads();

    // --- conv1 phase: P1 strip rows gpy = 8*qy-1 .. +8 (10), cols -1..32 ---
    for (int u = tid; u < 1360; u += 768) {
        int g = u / 170, t = u - g * 170;
        int py = t / 17, pxq = t - py * 17;

        ull acc[2][8];
        #pragma unroll
        for (int j = 0; j < 2; j++)
            #pragma unroll
            for (int q = 0; q < 8; q++) acc[j][q] = 0ull;

        #pragma unroll
        for (int ci = 0; ci < 4; ci++) {
            const float* ib = s_x + ci * 1584 + (2 * py) * 72 + 4 * pxq;
            const float* wp = s_w1 + ci * 288 + g * 4;
            CONV_CI_2P(ib, wp, 72, 32)
        }

        int gpy = 8 * qy - 1 + py;
        bool rowok = (unsigned)gpy < 32u;
        #pragma unroll
        for (int j = 0; j < 2; j++) {
            float v0[8], v1[8];
            #pragma unroll
            for (int q = 0; q < 8; q++) unpk(v0[q], v1[q], acc[j][q]);
            int co0 = g * 4 + 2 * j;
            float bb0 = b1[co0], bb1 = b1[co0 + 1];
            #pragma unroll
            for (int c2 = 0; c2 < 2; c2++) {
                float a0 = -1e30f, a1 = -1e30f;
                #pragma unroll
                for (int dy = 0; dy < 2; dy++)
                    #pragma unroll
                    for (int dx = 0; dx < 2; dx++) {
                        int q = dy * 4 + 2 * c2 + dx;
                        float t0 = v0[q] + bb0; t0 = LRELU(t0); a0 = fmaxf(a0, t0);
                        float t1 = v1[q] + bb1; t1 = LRELU(t1); a1 = fmaxf(a1, t1);
                    }
                int gpx = 2 * pxq + c2 - 1;
                bool ok = rowok && ((unsigned)gpx < 32u);
                int base = py * 36 + 2 * pxq + c2;
                s_p1[co0 * 360 + base]       = ok ? a0 : 0.f;
                s_p1[(co0 + 1) * 360 + base] = ok ? a1 : 0.f;
            }
        }
    }
    __syncthreads();

    // --- conv2 phase: 16 subs x 32 tiles = 512 slots; ci split 21 / 11 ---
    ull acc[2][8];
    #pragma unroll
    for (int j = 0; j < 2; j++)
        #pragma unroll
        for (int q = 0; q < 8; q++) acc[j][q] = 0ull;

    if (tid < 512) {
        const int sub = tid >> 5;
        const int t2 = tid & 31;
        const int gh = t2 >> 3, gw = t2 & 7;
        for (int ci = 0; ci < 21; ci++) {
            const float* ib = s_p1 + ci * 360 + (2 * gh) * 36 + 4 * gw;
            const float* wp = s_w2 + ci * 612 + sub * 4;
            CONV_CI_2P(ib, wp, 36, 68)
        }
    } else {
        const int e = tid - 512;       // 0..255, covers slots 2e and 2e+1
        #pragma unroll 1
        for (int sl = 0; sl < 2; sl++) {
            int slot = 2 * e + sl;
            const int sub = slot >> 5;
            const int t2 = slot & 31;
            const int gh = t2 >> 3, gw = t2 & 7;
            ull pacc[2][8];
            #pragma unroll
            for (int j = 0; j < 2; j++)
                #pragma unroll
                for (int q = 0; q < 8; q++) pacc[j][q] = 0ull;
            for (int ci = 21; ci < 32; ci++) {
                const float* ib = s_p1 + ci * 360 + (2 * gh) * 36 + 4 * gw;
                const float* wp = s_w2 + ci * 612 + sub * 4;
                {
                    LOAD_PATCH(ib, 36)
                    #pragma unroll
                    for (int k = 0; k < 9; k++) {
                        ulonglong2 w = *(const ulonglong2*)(wp + k * 68);
                        int ky = k / 3, kx = k - ky * 3;
                        #pragma unroll
                        for (int dy = 0; dy < 2; dy++)
                            #pragma unroll
                            for (int dx = 0; dx < 4; dx++) {
                                ull pv = pd[dy + ky][dx + kx];
                                int q = dy * 4 + dx;
                                ffma2(pacc[0][q], pv, w.x);
                                ffma2(pacc[1][q], pv, w.y);
                            }
                    }
                }
            }
            ull* sp = s_part + slot * 17;
            #pragma unroll
            for (int j = 0; j < 2; j++)
                #pragma unroll
                for (int q = 0; q < 8; q++) sp[j * 8 + q] = pacc[j][q];
        }
    }
    __syncthreads();

    if (tid < 512) {
        const int sub = tid >> 5;
        const int t2 = tid & 31;
        const int gh = t2 >> 3, gw = t2 & 7;
        ull* sp = s_part + tid * 17;
        #pragma unroll
        for (int j = 0; j < 2; j++)
            #pragma unroll
            for (int q = 0; q < 8; q++) acc[j][q] = addf2(acc[j][q], sp[j * 8 + q]);

        #pragma unroll
        for (int j = 0; j < 2; j++) {
            float v0[8], v1[8];
            #pragma unroll
            for (int q = 0; q < 8; q++) unpk(v0[q], v1[q], acc[j][q]);
            int co0 = sub * 4 + 2 * j;
            float bb0 = 4.f * b2[co0], bb1 = 4.f * b2[co0 + 1];
            float m0[2], m1[2];
            #pragma unroll
            for (int c2 = 0; c2 < 2; c2++) {
                float a0 = -1e30f, a1 = -1e30f;
                #pragma unroll
                for (int dy = 0; dy < 2; dy++)
                    #pragma unroll
                    for (int dx = 0; dx < 2; dx++) {
                        int q = dy * 4 + 2 * c2 + dx;
                        float t0 = fmaf(12.f, v0[q], bb0); t0 = LRELU(t0); a0 = fmaxf(a0, t0);
                        float t1 = fmaf(12.f, v1[q], bb1); t1 = LRELU(t1); a1 = fmaxf(a1, t1);
                    }
                m0[c2] = a0; m1[c2] = a1;
            }
            int row = 4 * qy + gh;
            *(float2*)(g_H2 + (b * 64 + co0) * 256 + row * 16 + 2 * gw) =
                make_float2(m0[0], m0[1]);
            *(float2*)(g_H2 + (b * 64 + co0 + 1) * 256 + row * 16 + 2 * gw) =
                make_float2(m1[0], m1[1]);
        }
    }
}

// ---------------------------------------------------------------------------
// Kernel 3: conv3 (64->128) + lrelu + pool + mean + dot(wc).  grid(32,4), 768.
// 3-way ci split (22/21/21); partials parked in s_in region (dead after conv),
// combined by third 0 with packed adds.
// ---------------------------------------------------------------------------
__global__ void __launch_bounds__(768, 1)
k3_conv(const float* __restrict__ w3,
        const float* __restrict__ b3,
        const float* __restrict__ wc,
        float* __restrict__ out) {
    extern __shared__ float sm[];
    float* s_in  = sm;                 // 64*360 = 23040 (reused for partials)
    float* s_w   = sm + 23040;         // 576*36 = 20736
    float* s_red = sm + 43776;         // 32*65 = 2080   (total 45856 fl)
    ull*   s_part = (ull*)sm;          // alias of s_in: 2*256*17 ull = 17408 fl

    const int b  = blockIdx.x;
    const int cg = blockIdx.y;
    const int tid = threadIdx.x;

    const float* hb = g_H2 + b * 16384;
    for (int j = tid; j < 4096; j += 768) {
        float4 v = *(const float4*)(hb + j * 4);
        int c = j >> 6, r = (j >> 2) & 15, x0 = (j & 3) * 4;
        float* d = s_in + c * 360 + (r + 1) * 20 + x0 + 1;
        d[0] = v.x; d[1] = v.y; d[2] = v.z; d[3] = v.w;
    }
    for (int i = tid; i < 64 * 72; i += 768) {
        int c = i / 72, t = i - c * 72;
        int row, col;
        if (t < 40) { row = (t >= 20) ? 17 : 0; col = t % 20; }
        else { int tt = t - 40; row = 1 + (tt >> 1); col = (tt & 1) ? 17 : 0; }
        s_in[c * 360 + row * 20 + col] = 0.f;
    }
    for (int i = tid * 4; i < 18432; i += 3072) {
        float4 wv = *(const float4*)(w3 + cg * 18432 + i);
        int co = i / 576, r = i - co * 576;
        s_w[(r + 0) * 36 + co] = wv.x;
        s_w[(r + 1) * 36 + co] = wv.y;
        s_w[(r + 2) * 36 + co] = wv.z;
        s_w[(r + 3) * 36 + co] = wv.w;
    }
    __syncthreads();

    const int h  = tid >> 8;           // 0..2 ci third
    const int wt = tid & 255;          // worker id
    const int sub = wt >> 5;           // 0..7 -> couts sub*4..+3
    const int pxg = wt & 31;
    const int gh = pxg >> 2, gw = pxg & 3;

    ull acc[2][8];
    #pragma unroll
    for (int j = 0; j < 2; j++)
        #pragma unroll
        for (int q = 0; q < 8; q++) acc[j][q] = 0ull;

    const int cib = (h == 0) ? 0 : (h == 1 ? 22 : 43);
    const int cie = (h == 0) ? 22 : (h == 1 ? 43 : 64);
    for (int ci = cib; ci < cie; ci++) {
        const float* ib = s_in + ci * 360 + (2 * gh) * 20 + 4 * gw;
        const float* wp = s_w + ci * 324 + sub * 4;
        CONV_CI_2P(ib, wp, 20, 36)
    }
    __syncthreads();                   // everyone done READING s_in

    if (h) {
        ull* sp = s_part + ((h - 1) * 256 + wt) * 17;
        #pragma unroll
        for (int j = 0; j < 2; j++)
            #pragma unroll
            for (int q = 0; q < 8; q++) sp[j * 8 + q] = acc[j][q];
    }
    __syncthreads();

    if (!h) {
        ull* sp1 = s_part + wt * 17;
        ull* sp2 = s_part + (256 + wt) * 17;
        #pragma unroll
        for (int j = 0; j < 2; j++)
            #pragma unroll
            for (int q = 0; q < 8; q++) {
                acc[j][q] = addf2(acc[j][q], sp1[j * 8 + q]);
                acc[j][q] = addf2(acc[j][q], sp2[j * 8 + q]);
            }

        #pragma unroll
        for (int j = 0; j < 2; j++) {
            float v0[8], v1[8];
            #pragma unroll
            for (int q = 0; q < 8; q++) unpk(v0[q], v1[q], acc[j][q]);
            int lco0 = sub * 4 + 2 * j;
            float bb0 = b3[cg * 32 + lco0], bb1 = b3[cg * 32 + lco0 + 1];
            #pragma unroll
            for (int c2 = 0; c2 < 2; c2++) {
                float a0 = -1e30f, a1 = -1e30f;
                #pragma unroll
                for (int dy = 0; dy < 2; dy++)
                    #pragma unroll
                    for (int dx = 0; dx < 2; dx++) {
                        int q = dy * 4 + 2 * c2 + dx;
                        float t0 = v0[q] + bb0; t0 = LRELU(t0); a0 = fmaxf(a0, t0);
                        float t1 = v1[q] + bb1; t1 = LRELU(t1); a1 = fmaxf(a1, t1);
                    }
                int ppx = gh * 8 + 2 * gw + c2;
                s_red[lco0 * 65 + ppx] = a0;
                s_red[(lco0 + 1) * 65 + ppx] = a1;
            }
        }
    }
    __syncthreads();

    if (tid < 32) {
        float s = 0.f;
        #pragma unroll 8
        for (int p2 = 0; p2 < 64; p2++) s += s_red[tid * 65 + p2];
        float part = wc[cg * 32 + tid] * s * (1.0f / 64.0f);
        #pragma unroll
        for (int off = 16; off; off >>= 1)
            part += __shfl_down_sync(0xffffffffu, part, off);
        if (tid == 0) atomicAdd(&out[b], part);
    }
}

extern "C" void kernel_launch(void* const* d_in, const int* in_sizes, int n_in,
                              void* d_out, int out_size) {
    const float* x  = (const float*)d_in[0];
    const float* w1 = (const float*)d_in[1];
    const float* b1 = (const float*)d_in[2];
    const float* w2 = (const float*)d_in[3];
    const float* b2 = (const float*)d_in[4];
    const float* w3 = (const float*)d_in[5];
    const float* b3 = (const float*)d_in[6];
    const float* wc = (const float*)d_in[7];
    const float* bc = (const float*)d_in[8];
    float* out = (float*)d_out;

    const size_t sm12 = 56000 * sizeof(float);                  // 218.75 KB
    const size_t sm3  = 45856 * sizeof(float);                  // 179.1 KB

    cudaFuncSetAttribute(k12_conv, cudaFuncAttributeMaxDynamicSharedMemorySize, (int)sm12);
    cudaFuncSetAttribute(k3_conv,  cudaFuncAttributeMaxDynamicSharedMemorySize, (int)sm3);

    k12_conv<<<dim3(32, 4), 768, sm12>>>(x, w1, b1, w2, b2, bc, out);
    k3_conv<<<dim3(32, 4), 768, sm3>>>(w3, b3, wc, out);
}